// round 7
// baseline (speedup 1.0000x reference)
#include <cuda_runtime.h>
#include <math.h>
#include <stdint.h>

#define B_     4096
#define D_     512
#define H_     512
#define V_     128
#define MAXLEN 100
#define TH3    1536   // 3*H

typedef uint32_t u32;
typedef unsigned long long u64;

// ------------------------- persistent device scratch -------------------------
__device__ float g_h0[2][B_ * H_];
__device__ float g_h1[2][B_ * H_];
__device__ float g_zc0p[B_ * TH3];        // z @ Wih0[:,H:]^T + bih0 (gate-interleaved)
__device__ float g_T0p[V_ * TH3];         // emb @ Wih0[:,:H]^T (gate-interleaved)
__device__ float g_Whh0p[TH3 * H_];       // permuted: row j*3+g = Whh0[g*H+j]
__device__ float g_Wih1p[TH3 * H_];
__device__ float g_Whh1p[TH3 * H_];
__device__ float g_Wih0ep[TH3 * H_];
__device__ float g_Wih0zp[TH3 * H_];
__device__ float g_bhh0p[TH3];
__device__ float g_bi1p[TH3];
__device__ float g_bh1p[TH3];
__device__ float g_bih0p[TH3];
__device__ float g_outWt[H_ * V_];
__device__ int   g_w[B_];
__device__ int   g_eos[B_];

// --------- accurate, fast-math-immune exp / sigmoid / tanh (identical to R3 pass) ---------
__device__ __forceinline__ float exp_acc(float x) {
    x = fminf(fmaxf(x, -87.0f), 88.0f);
    float k = rintf(x * 1.4426950408889634f);
    float f = fmaf(k, -0.693359375f, x);
    f = fmaf(k, 2.12194440e-4f, f);
    float z = f * f;
    float p = 1.9875691500e-4f;
    p = fmaf(p, f, 1.3981999507e-3f);
    p = fmaf(p, f, 8.3334519073e-3f);
    p = fmaf(p, f, 4.1665795894e-2f);
    p = fmaf(p, f, 1.6666665459e-1f);
    p = fmaf(p, f, 5.0000001201e-1f);
    float y = fmaf(p, z, f) + 1.0f;
    return __int_as_float(__float_as_int(y) + (((int)k) << 23));
}
__device__ __forceinline__ float sigmoidf_(float x) { return 1.0f / (1.0f + exp_acc(-x)); }
__device__ __forceinline__ float tanhf_(float x) {
    float e = exp_acc(2.0f * x);
    return (e - 1.0f) / (e + 1.0f);
}

// --------- packed fp32x2 FMA: two independent IEEE fp32 RN fmas per issue ---------
__device__ __forceinline__ void fma2(u64& d, u64 a, u64 b) {
    asm("fma.rn.f32x2 %0, %1, %2, %3;" : "=l"(d) : "l"(a), "l"(b), "l"(d));
}
__device__ __forceinline__ u64 dup_f32(float v) {
    u32 b = __float_as_uint(v);
    return ((u64)b << 32) | (u64)b;
}

// ------------------------- init: weight permutation -------------------------
__global__ void permute_kernel(const float* __restrict__ Wih0,
                               const float* __restrict__ Whh0,
                               const float* __restrict__ Wih1,
                               const float* __restrict__ Whh1,
                               const float* __restrict__ bih0,
                               const float* __restrict__ bhh0,
                               const float* __restrict__ bih1,
                               const float* __restrict__ bhh1,
                               const float* __restrict__ outW) {
    int idx = blockIdx.x * blockDim.x + threadIdx.x;
    if (idx < TH3 * H_) {
        int c = idx / H_;
        int k = idx - c * H_;
        int j = c / 3, g = c - 3 * (c / 3);
        int src = g * H_ + j;
        g_Whh0p[idx]  = Whh0[src * H_ + k];
        g_Wih1p[idx]  = Wih1[src * H_ + k];
        g_Whh1p[idx]  = Whh1[src * H_ + k];
        g_Wih0ep[idx] = Wih0[src * (H_ + D_) + k];
        g_Wih0zp[idx] = Wih0[src * (H_ + D_) + H_ + k];
        if (k == 0) {
            g_bhh0p[c] = bhh0[src];
            g_bi1p[c]  = bih1[src];
            g_bh1p[c]  = bhh1[src];
            g_bih0p[c] = bih0[src];
        }
    }
    if (idx < H_ * V_) {
        int k = idx / V_, v = idx - k * V_;
        g_outWt[idx] = outW[v * H_ + k];
    }
}

__global__ void init_state_kernel(float* __restrict__ xout, float* __restrict__ endp) {
    int b = blockIdx.x * blockDim.x + threadIdx.x;
    if (b < B_) {
        g_w[b]   = 1;
        g_eos[b] = 0;
        if (endp) endp[b] = (float)MAXLEN;
        xout[b * MAXLEN] = 1.0f;
    }
}

// ------------------------- init GEMMs (fp32 FFMA, one-time; identical to R3) -------------------------
__global__ void __launch_bounds__(256) gemm_init_kernel(const float* __restrict__ A,
                                                        const float* __restrict__ Wext,
                                                        const float* __restrict__ biasext,
                                                        int mode) {
    const float* W;
    const float* bias;
    float* C;
    float* C2 = nullptr;
    int N;
    if (mode == 0)      { W = Wext;      bias = biasext;  C = g_h0[0]; C2 = g_h1[0]; N = H_;  }
    else if (mode == 1) { W = g_Wih0zp;  bias = g_bih0p;  C = g_zc0p;  N = TH3; }
    else                { W = g_Wih0ep;  bias = nullptr;  C = g_T0p;   N = TH3; }

    __shared__ float As[16][64];
    __shared__ float Bs[16][64];
    int bm = blockIdx.y * 64, bn = blockIdx.x * 64;
    int tid = threadIdx.x;
    int tx = tid & 15, ty = tid >> 4;
    float acc[4][4] = {};

    for (int kt = 0; kt < H_; kt += 16) {
        int r = tid >> 2, kc = (tid & 3) * 4;
        float4 va = *(const float4*)(A + (size_t)(bm + r) * H_ + kt + kc);
        float4 vb = *(const float4*)(W + (size_t)(bn + r) * H_ + kt + kc);
        As[kc + 0][r] = va.x; As[kc + 1][r] = va.y; As[kc + 2][r] = va.z; As[kc + 3][r] = va.w;
        Bs[kc + 0][r] = vb.x; Bs[kc + 1][r] = vb.y; Bs[kc + 2][r] = vb.z; Bs[kc + 3][r] = vb.w;
        __syncthreads();
#pragma unroll
        for (int kk = 0; kk < 16; kk++) {
            float a[4], b[4];
            *(float4*)a = *(const float4*)&As[kk][ty * 4];
            *(float4*)b = *(const float4*)&Bs[kk][tx * 4];
#pragma unroll
            for (int i = 0; i < 4; i++)
#pragma unroll
                for (int j = 0; j < 4; j++) acc[i][j] += a[i] * b[j];
        }
        __syncthreads();
    }
#pragma unroll
    for (int i = 0; i < 4; i++) {
        int row = bm + ty * 4 + i;
#pragma unroll
        for (int j = 0; j < 4; j++) {
            int col = bn + tx * 4 + j;
            float v = acc[i][j] + (bias ? bias[col] : 0.0f);
            C[(size_t)row * N + col] = v;
            if (C2) C2[(size_t)row * N + col] = v;
        }
    }
}

// ============================================================================
// layer0 (FFMA2): gh = h0 @ Whh0p^T (BM=128 x BN=96, 32 h-indices); GRU -> h0'
// acc packed along rows: acc(row_pair, col) = fma2(a_pair, dup(b), acc)
// Bit-identical per element to the scalar-FFMA round-3 kernel.
// ============================================================================
__global__ void __launch_bounds__(256) layer0_f2(int p) {
    const float* __restrict__ hcur  = g_h0[p ^ 1];
    float*       __restrict__ hnext = g_h0[p];

    __shared__ __align__(16) unsigned char sm[49152];
    float* As = (float*)sm;                 // [16][132] = 8448 B
    u64*   Bs = (u64*)(sm + 8448);          // [16][96] dup'd = 12288 B (end 20736)
    float* Cs = (float*)sm;                 // [128][96] = 49152 B (reused after loop)

    int tid = threadIdx.x;
    int tx = tid & 15, ty = tid >> 4;
    int bm = blockIdx.y * 128;
    int j0 = blockIdx.x * 32;
    int c0 = j0 * 3;

    u64 acc[4][6] = {};   // rows (ty*8+2ip, +1), cols tx+16m

    for (int kt = 0; kt < H_; kt += 16) {
        __syncthreads();
        // stage A: [k][row], pad 132
        {
            int r = tid >> 1, kc = (tid & 1) * 8;
            const float* src = hcur + (size_t)(bm + r) * H_ + kt + kc;
            float4 v0 = *(const float4*)src;
            float4 v1 = *(const float4*)(src + 4);
            float e[8] = {v0.x, v0.y, v0.z, v0.w, v1.x, v1.y, v1.z, v1.w};
#pragma unroll
            for (int i2 = 0; i2 < 8; i2++) As[(kc + i2) * 132 + r] = e[i2];
        }
        // stage B: dup'd pairs [k][col]
        for (int i = tid; i < 384; i += 256) {
            int col = i % 96, kq = i / 96;
            const float* w = g_Whh0p + (size_t)(c0 + col) * H_ + kt + kq * 4;
            float4 v = *(const float4*)w;
            Bs[(kq * 4 + 0) * 96 + col] = dup_f32(v.x);
            Bs[(kq * 4 + 1) * 96 + col] = dup_f32(v.y);
            Bs[(kq * 4 + 2) * 96 + col] = dup_f32(v.z);
            Bs[(kq * 4 + 3) * 96 + col] = dup_f32(v.w);
        }
        __syncthreads();
#pragma unroll
        for (int kk = 0; kk < 16; kk++) {
            ulonglong2 a01 = *(const ulonglong2*)&As[kk * 132 + ty * 8];
            ulonglong2 a23 = *(const ulonglong2*)&As[kk * 132 + ty * 8 + 4];
            u64 ap[4] = {a01.x, a01.y, a23.x, a23.y};
#pragma unroll
            for (int m = 0; m < 6; m++) {
                u64 bd = Bs[kk * 96 + tx + 16 * m];
#pragma unroll
                for (int ip = 0; ip < 4; ip++) fma2(acc[ip][m], ap[ip], bd);
            }
        }
    }
    __syncthreads();
    // stage accumulators to Cs[row][col]
#pragma unroll
    for (int ip = 0; ip < 4; ip++) {
#pragma unroll
        for (int m = 0; m < 6; m++) {
            float2 f = *(float2*)&acc[ip][m];
            int ro = ty * 8 + 2 * ip;
            int col = tx + 16 * m;
            Cs[ro * 96 + col]       = f.x;
            Cs[(ro + 1) * 96 + col] = f.y;
        }
    }
    __syncthreads();
    // GRU epilogue: 128 rows x 32 h-indices
#pragma unroll
    for (int pass = 0; pass < 16; pass++) {
        int idx = pass * 256 + tid;
        int row = idx >> 5, jl = idx & 31;
        int b = bm + row;
        int j = j0 + jl;
        int cg = j * 3;
        int cl = jl * 3;
        int wt = g_w[b];
        const float* Trow = &g_T0p[wt * TH3];
        const float* Zrow = &g_zc0p[(size_t)b * TH3];
        float gi0 = Trow[cg]     + Zrow[cg];
        float gi1 = Trow[cg + 1] + Zrow[cg + 1];
        float gi2 = Trow[cg + 2] + Zrow[cg + 2];
        float gh0 = Cs[row * 96 + cl]     + g_bhh0p[cg];
        float gh1 = Cs[row * 96 + cl + 1] + g_bhh0p[cg + 1];
        float gh2 = Cs[row * 96 + cl + 2] + g_bhh0p[cg + 2];
        float rg = sigmoidf_(gi0 + gh0);
        float zg = sigmoidf_(gi1 + gh1);
        float nn = tanhf_(gi2 + rg * gh2);
        float hp = hcur[(size_t)b * H_ + j];
        hnext[(size_t)b * H_ + j] = (1.0f - zg) * nn + zg * hp;
    }
}

// ============================================================================
// layer1 (FFMA2 dual GEMM): gi = h_l0 @ Wih1p^T, gh = h1 @ Whh1p^T (BN=48); GRU
// ============================================================================
__global__ void __launch_bounds__(256) layer1_f2(int p) {
    const float* __restrict__ x     = g_h0[p];
    const float* __restrict__ hcur  = g_h1[p ^ 1];
    float*       __restrict__ hnext = g_h1[p];

    __shared__ __align__(16) unsigned char sm[49152];
    float* Ax = (float*)sm;                  // [16][132] 8448
    float* Ah = (float*)(sm + 8448);         // [16][132] 8448
    u64*   Bi = (u64*)(sm + 16896);          // [16][48]  6144
    u64*   Bh = (u64*)(sm + 23040);          // [16][48]  6144 (end 29184)
    float* Ci = (float*)sm;                  // [128][48] 24576
    float* Ch = (float*)(sm + 24576);        // [128][48] 24576 (end 49152)

    int tid = threadIdx.x;
    int tx = tid & 15, ty = tid >> 4;
    int bm = blockIdx.y * 128;
    int j0 = blockIdx.x * 16;
    int c0 = j0 * 3;

    u64 acc_i[4][3] = {};
    u64 acc_h[4][3] = {};

    for (int kt = 0; kt < H_; kt += 16) {
        __syncthreads();
        {
            int r = tid >> 1, kc = (tid & 1) * 8;
            const float* sx = x    + (size_t)(bm + r) * H_ + kt + kc;
            const float* sh = hcur + (size_t)(bm + r) * H_ + kt + kc;
            float4 v0 = *(const float4*)sx;
            float4 v1 = *(const float4*)(sx + 4);
            float4 w0 = *(const float4*)sh;
            float4 w1 = *(const float4*)(sh + 4);
            float ex[8] = {v0.x, v0.y, v0.z, v0.w, v1.x, v1.y, v1.z, v1.w};
            float eh[8] = {w0.x, w0.y, w0.z, w0.w, w1.x, w1.y, w1.z, w1.w};
#pragma unroll
            for (int i2 = 0; i2 < 8; i2++) {
                Ax[(kc + i2) * 132 + r] = ex[i2];
                Ah[(kc + i2) * 132 + r] = eh[i2];
            }
        }
        for (int i = tid; i < 384; i += 256) {
            int half = (i >= 192);
            int ii = i - half * 192;
            int col = ii % 48, kq = ii / 48;
            const float* wsrc = half ? g_Whh1p : g_Wih1p;
            u64* Bdst = half ? Bh : Bi;
            const float* w = wsrc + (size_t)(c0 + col) * H_ + kt + kq * 4;
            float4 v = *(const float4*)w;
            Bdst[(kq * 4 + 0) * 48 + col] = dup_f32(v.x);
            Bdst[(kq * 4 + 1) * 48 + col] = dup_f32(v.y);
            Bdst[(kq * 4 + 2) * 48 + col] = dup_f32(v.z);
            Bdst[(kq * 4 + 3) * 48 + col] = dup_f32(v.w);
        }
        __syncthreads();
#pragma unroll
        for (int kk = 0; kk < 16; kk++) {
            ulonglong2 x01 = *(const ulonglong2*)&Ax[kk * 132 + ty * 8];
            ulonglong2 x23 = *(const ulonglong2*)&Ax[kk * 132 + ty * 8 + 4];
            ulonglong2 h01 = *(const ulonglong2*)&Ah[kk * 132 + ty * 8];
            ulonglong2 h23 = *(const ulonglong2*)&Ah[kk * 132 + ty * 8 + 4];
            u64 xp[4] = {x01.x, x01.y, x23.x, x23.y};
            u64 hp[4] = {h01.x, h01.y, h23.x, h23.y};
#pragma unroll
            for (int m = 0; m < 3; m++) {
                u64 bi = Bi[kk * 48 + tx + 16 * m];
                u64 bh = Bh[kk * 48 + tx + 16 * m];
#pragma unroll
                for (int ip = 0; ip < 4; ip++) {
                    fma2(acc_i[ip][m], xp[ip], bi);
                    fma2(acc_h[ip][m], hp[ip], bh);
                }
            }
        }
    }
    __syncthreads();
#pragma unroll
    for (int ip = 0; ip < 4; ip++) {
#pragma unroll
        for (int m = 0; m < 3; m++) {
            int ro = ty * 8 + 2 * ip;
            int col = tx + 16 * m;
            float2 fi = *(float2*)&acc_i[ip][m];
            float2 fh = *(float2*)&acc_h[ip][m];
            Ci[ro * 48 + col]       = fi.x;
            Ci[(ro + 1) * 48 + col] = fi.y;
            Ch[ro * 48 + col]       = fh.x;
            Ch[(ro + 1) * 48 + col] = fh.y;
        }
    }
    __syncthreads();
#pragma unroll
    for (int pass = 0; pass < 8; pass++) {
        int idx = pass * 256 + tid;
        int row = idx >> 4, jl = idx & 15;
        int b = bm + row;
        int j = j0 + jl;
        int cg = j * 3;
        int cl = jl * 3;
        float gi0 = Ci[row * 48 + cl]     + g_bi1p[cg];
        float gi1 = Ci[row * 48 + cl + 1] + g_bi1p[cg + 1];
        float gi2 = Ci[row * 48 + cl + 2] + g_bi1p[cg + 2];
        float gh0 = Ch[row * 48 + cl]     + g_bh1p[cg];
        float gh1 = Ch[row * 48 + cl + 1] + g_bh1p[cg + 1];
        float gh2 = Ch[row * 48 + cl + 2] + g_bh1p[cg + 2];
        float rg = sigmoidf_(gi0 + gh0);
        float zg = sigmoidf_(gi1 + gh1);
        float nn = tanhf_(gi2 + rg * gh2);
        float hp = hcur[(size_t)b * H_ + j];
        hnext[(size_t)b * H_ + j] = (1.0f - zg) * nn + zg * hp;
    }
}

// ------------------------- logits + argmax + token logic (identical to R3) -------------------------
__global__ void __launch_bounds__(128) logits_kernel(int p, const float* __restrict__ out_b,
                                                     float* __restrict__ xout,
                                                     float* __restrict__ endp, int step) {
    const float* __restrict__ h = g_h1[p];
    __shared__ float Hs[16 * H_];
    __shared__ float Ls[16][V_];
    int b0 = blockIdx.x * 16;
    int tid = threadIdx.x;

    const float4* src = (const float4*)(h + (size_t)b0 * H_);
    float4* dst = (float4*)Hs;
    for (int i = tid; i < 16 * H_ / 4; i += 128) dst[i] = src[i];
    __syncthreads();

    float acc[16];
#pragma unroll
    for (int r = 0; r < 16; r++) acc[r] = 0.0f;

    for (int k = 0; k < H_; k += 4) {
        float w0 = g_outWt[(k + 0) * V_ + tid];
        float w1 = g_outWt[(k + 1) * V_ + tid];
        float w2 = g_outWt[(k + 2) * V_ + tid];
        float w3 = g_outWt[(k + 3) * V_ + tid];
#pragma unroll
        for (int r = 0; r < 16; r++) {
            float4 hv = *(const float4*)&Hs[r * H_ + k];
            acc[r] += hv.x * w0 + hv.y * w1 + hv.z * w2 + hv.w * w3;
        }
    }
    float bb = out_b[tid];
#pragma unroll
    for (int r = 0; r < 16; r++) Ls[r][tid] = acc[r] + bb;
    __syncthreads();

    if (tid < 16) {
        int b = b0 + tid;
        const float* row = Ls[tid];
        float best = row[0];
        int bi = 0;
        for (int v = 1; v < V_; v++) {
            float xv = row[v];
            if (xv > best) { best = xv; bi = v; }
        }
        int eo = g_eos[b];
        xout[b * MAXLEN + step] = eo ? 0.0f : (float)bi;
        if (!eo && bi == 2) {
            if (endp) endp[b] = (float)(step + 1);
            g_eos[b] = 1;
        }
        g_w[b] = bi;
    }
}

// ------------------------- launch -------------------------
extern "C" void kernel_launch(void* const* d_in, const int* in_sizes, int n_in,
                              void* d_out, int out_size) {
    static const int want[14] = {
        B_ * D_, V_ * H_, H_ * D_, H_,
        TH3 * (H_ + D_), TH3 * H_, TH3, TH3,
        TH3 * H_, TH3 * H_, TH3, TH3,
        V_ * H_, V_
    };
    const float* in[14];
    bool used[14] = {};
    bool ok = (n_in >= 14);
    for (int i = 0; i < 14 && ok; i++) {
        int found = -1;
        for (int j = 0; j < 14; j++) {
            if (!used[j] && in_sizes[j] == want[i]) { found = j; break; }
        }
        if (found < 0) { ok = false; break; }
        used[found] = true;
        in[i] = (const float*)d_in[found];
    }
    if (!ok) {
        for (int i = 0; i < 14; i++) in[i] = (const float*)d_in[i];
    }
    const float* z     = in[0];
    const float* lat_W = in[2];
    const float* lat_b = in[3];
    const float* out_b = in[13];

    float* xout = (float*)d_out;
    float* endp = nullptr;
    if (out_size >= B_ * MAXLEN + B_) {
        endp = xout + (out_size - B_);
    }

    permute_kernel<<<(TH3 * H_ + 255) / 256, 256>>>(in[4], in[5], in[8], in[9],
                                                    in[6], in[7], in[10], in[11], in[12]);
    init_state_kernel<<<(B_ + 255) / 256, 256>>>(xout, endp);
    gemm_init_kernel<<<dim3(H_ / 64, B_ / 64), 256>>>(z, lat_W, lat_b, 0);
    gemm_init_kernel<<<dim3(TH3 / 64, B_ / 64), 256>>>(z, nullptr, nullptr, 1);
    gemm_init_kernel<<<dim3(TH3 / 64, V_ / 64), 256>>>(in[1], nullptr, nullptr, 2);

    for (int s = 1; s < MAXLEN; s++) {
        int p = s & 1;
        layer0_f2<<<dim3(H_ / 32, B_ / 128), 256>>>(p);
        layer1_f2<<<dim3(H_ / 16, B_ / 128), 256>>>(p);
        logits_kernel<<<B_ / 16, 128>>>(p, out_b, xout, endp, s);
    }
}

// round 8
// speedup vs baseline: 1.3593x; 1.3593x over previous
#include <cuda_runtime.h>
#include <math.h>
#include <stdint.h>

#define B_     4096
#define D_     512
#define H_     512
#define V_     128
#define MAXLEN 100
#define TH3    1536   // 3*H

// ------------------------- persistent device scratch -------------------------
__device__ float g_h0[2][B_ * H_];
__device__ float g_h1[2][B_ * H_];
__device__ float g_zc0p[B_ * TH3];        // z @ Wih0[:,H:]^T + bih0 (gate-interleaved)
__device__ float g_T0p[V_ * TH3];         // emb @ Wih0[:,:H]^T (gate-interleaved)
__device__ float g_Whh0p[TH3 * H_];       // permuted: row j*3+g = Whh0[g*H+j]
__device__ float g_Wih1p[TH3 * H_];
__device__ float g_Whh1p[TH3 * H_];
__device__ float g_Wih0ep[TH3 * H_];
__device__ float g_Wih0zp[TH3 * H_];
__device__ float g_bhh0p[TH3];
__device__ float g_bi1p[TH3];
__device__ float g_bh1p[TH3];
__device__ float g_bih0p[TH3];
__device__ float g_outWt[H_ * V_];
__device__ float g_gi[B_ * TH3];          // layer1 input-GEMM scratch
__device__ float g_gh[B_ * TH3];          // layer1 hidden-GEMM scratch
__device__ int   g_w[B_];
__device__ int   g_eos[B_];

// --------- accurate, fast-math-immune exp / sigmoid / tanh (identical to R3 pass) ---------
__device__ __forceinline__ float exp_acc(float x) {
    x = fminf(fmaxf(x, -87.0f), 88.0f);
    float k = rintf(x * 1.4426950408889634f);
    float f = fmaf(k, -0.693359375f, x);
    f = fmaf(k, 2.12194440e-4f, f);
    float z = f * f;
    float p = 1.9875691500e-4f;
    p = fmaf(p, f, 1.3981999507e-3f);
    p = fmaf(p, f, 8.3334519073e-3f);
    p = fmaf(p, f, 4.1665795894e-2f);
    p = fmaf(p, f, 1.6666665459e-1f);
    p = fmaf(p, f, 5.0000001201e-1f);
    float y = fmaf(p, z, f) + 1.0f;
    return __int_as_float(__float_as_int(y) + (((int)k) << 23));
}
__device__ __forceinline__ float sigmoidf_(float x) { return 1.0f / (1.0f + exp_acc(-x)); }
__device__ __forceinline__ float tanhf_(float x) {
    float e = exp_acc(2.0f * x);
    return (e - 1.0f) / (e + 1.0f);
}

// ------------------------- init: weight permutation -------------------------
__global__ void permute_kernel(const float* __restrict__ Wih0,
                               const float* __restrict__ Whh0,
                               const float* __restrict__ Wih1,
                               const float* __restrict__ Whh1,
                               const float* __restrict__ bih0,
                               const float* __restrict__ bhh0,
                               const float* __restrict__ bih1,
                               const float* __restrict__ bhh1,
                               const float* __restrict__ outW) {
    int idx = blockIdx.x * blockDim.x + threadIdx.x;
    if (idx < TH3 * H_) {
        int c = idx / H_;
        int k = idx - c * H_;
        int j = c / 3, g = c - 3 * (c / 3);
        int src = g * H_ + j;
        g_Whh0p[idx]  = Whh0[src * H_ + k];
        g_Wih1p[idx]  = Wih1[src * H_ + k];
        g_Whh1p[idx]  = Whh1[src * H_ + k];
        g_Wih0ep[idx] = Wih0[src * (H_ + D_) + k];
        g_Wih0zp[idx] = Wih0[src * (H_ + D_) + H_ + k];
        if (k == 0) {
            g_bhh0p[c] = bhh0[src];
            g_bi1p[c]  = bih1[src];
            g_bh1p[c]  = bhh1[src];
            g_bih0p[c] = bih0[src];
        }
    }
    if (idx < H_ * V_) {
        int k = idx / V_, v = idx - k * V_;
        g_outWt[idx] = outW[v * H_ + k];
    }
}

__global__ void init_state_kernel(float* __restrict__ xout, float* __restrict__ endp) {
    int b = blockIdx.x * blockDim.x + threadIdx.x;
    if (b < B_) {
        g_w[b]   = 1;
        g_eos[b] = 0;
        if (endp) endp[b] = (float)MAXLEN;
        xout[b * MAXLEN] = 1.0f;
    }
}

// ------------------------- init GEMMs (fp32 FFMA, one-time; identical to R3) -------------------------
__global__ void __launch_bounds__(256) gemm_init_kernel(const float* __restrict__ A,
                                                        const float* __restrict__ Wext,
                                                        const float* __restrict__ biasext,
                                                        int mode) {
    const float* W;
    const float* bias;
    float* C;
    float* C2 = nullptr;
    int N;
    if (mode == 0)      { W = Wext;      bias = biasext;  C = g_h0[0]; C2 = g_h1[0]; N = H_;  }
    else if (mode == 1) { W = g_Wih0zp;  bias = g_bih0p;  C = g_zc0p;  N = TH3; }
    else                { W = g_Wih0ep;  bias = nullptr;  C = g_T0p;   N = TH3; }

    __shared__ float As[16][64];
    __shared__ float Bs[16][64];
    int bm = blockIdx.y * 64, bn = blockIdx.x * 64;
    int tid = threadIdx.x;
    int tx = tid & 15, ty = tid >> 4;
    float acc[4][4] = {};

    for (int kt = 0; kt < H_; kt += 16) {
        int r = tid >> 2, kc = (tid & 3) * 4;
        float4 va = *(const float4*)(A + (size_t)(bm + r) * H_ + kt + kc);
        float4 vb = *(const float4*)(W + (size_t)(bn + r) * H_ + kt + kc);
        As[kc + 0][r] = va.x; As[kc + 1][r] = va.y; As[kc + 2][r] = va.z; As[kc + 3][r] = va.w;
        Bs[kc + 0][r] = vb.x; Bs[kc + 1][r] = vb.y; Bs[kc + 2][r] = vb.z; Bs[kc + 3][r] = vb.w;
        __syncthreads();
#pragma unroll
        for (int kk = 0; kk < 16; kk++) {
            float a[4], b[4];
            *(float4*)a = *(const float4*)&As[kk][ty * 4];
            *(float4*)b = *(const float4*)&Bs[kk][tx * 4];
#pragma unroll
            for (int i = 0; i < 4; i++)
#pragma unroll
                for (int j = 0; j < 4; j++) acc[i][j] += a[i] * b[j];
        }
        __syncthreads();
    }
#pragma unroll
    for (int i = 0; i < 4; i++) {
        int row = bm + ty * 4 + i;
#pragma unroll
        for (int j = 0; j < 4; j++) {
            int col = bn + tx * 4 + j;
            float v = acc[i][j] + (bias ? bias[col] : 0.0f);
            C[(size_t)row * N + col] = v;
            if (C2) C2[(size_t)row * N + col] = v;
        }
    }
}

// ============================================================================
// layer0_k: fused gh0 GEMM (BM=64 x 48 cols = 16 h) + GRU epilogue.
// 64 threads; per-thread 8 rows x 6 cols (= 2 complete gate triples).
// Fine tiles -> 2048 blocks -> per-SM work balance ~98.9%.
// ============================================================================
#define ASTR 68
#define BSTR 50

__global__ void __launch_bounds__(64) layer0_k(int p) {
    const float* __restrict__ hcur  = g_h0[p ^ 1];
    float*       __restrict__ hnext = g_h0[p];

    __shared__ float As[16 * ASTR];
    __shared__ float Bs[16 * BSTR];

    int tid = threadIdx.x;
    int bm = blockIdx.y * 64;
    int j0 = blockIdx.x * 16;
    int c0 = j0 * 3;
    int rg = (tid >> 3) * 8;       // row group base (0..56)
    int cg = (tid & 7) * 6;        // col group base (0..42)

    float acc[8][6] = {};

    for (int kt = 0; kt < H_; kt += 16) {
        __syncthreads();
#pragma unroll
        for (int pp = 0; pp < 4; pp++) {
            int r = (tid >> 2) + 16 * pp, kc = (tid & 3) * 4;
            float4 v = *(const float4*)(hcur + (size_t)(bm + r) * H_ + kt + kc);
            As[(kc + 0) * ASTR + r] = v.x;
            As[(kc + 1) * ASTR + r] = v.y;
            As[(kc + 2) * ASTR + r] = v.z;
            As[(kc + 3) * ASTR + r] = v.w;
        }
#pragma unroll
        for (int s = 0; s < 3; s++) {
            int i = tid + 64 * s;
            int col = i >> 2, kc = (i & 3) * 4;
            float4 v = *(const float4*)(g_Whh0p + (size_t)(c0 + col) * H_ + kt + kc);
            Bs[(kc + 0) * BSTR + col] = v.x;
            Bs[(kc + 1) * BSTR + col] = v.y;
            Bs[(kc + 2) * BSTR + col] = v.z;
            Bs[(kc + 3) * BSTR + col] = v.w;
        }
        __syncthreads();
#pragma unroll
        for (int kk = 0; kk < 16; kk++) {
            float a[8], b[6];
            *(float4*)&a[0] = *(const float4*)&As[kk * ASTR + rg];
            *(float4*)&a[4] = *(const float4*)&As[kk * ASTR + rg + 4];
            *(float2*)&b[0] = *(const float2*)&Bs[kk * BSTR + cg];
            *(float2*)&b[2] = *(const float2*)&Bs[kk * BSTR + cg + 2];
            *(float2*)&b[4] = *(const float2*)&Bs[kk * BSTR + cg + 4];
#pragma unroll
            for (int i = 0; i < 8; i++)
#pragma unroll
                for (int j = 0; j < 6; j++) acc[i][j] += a[i] * b[j];
        }
    }
    // fused GRU epilogue (triples live in registers: cols cg..cg+5 = 2 h-units)
#pragma unroll
    for (int i = 0; i < 8; i++) {
        int b = bm + rg + i;
        int wt = g_w[b];
        const float* Trow = &g_T0p[wt * TH3];
        const float* Zrow = &g_zc0p[(size_t)b * TH3];
#pragma unroll
        for (int hh = 0; hh < 2; hh++) {
            int j = j0 + (tid & 7) * 2 + hh;
            int c = j * 3;
            float gi0 = Trow[c]     + Zrow[c];
            float gi1 = Trow[c + 1] + Zrow[c + 1];
            float gi2 = Trow[c + 2] + Zrow[c + 2];
            float gh0 = acc[i][hh * 3 + 0] + g_bhh0p[c];
            float gh1 = acc[i][hh * 3 + 1] + g_bhh0p[c + 1];
            float gh2 = acc[i][hh * 3 + 2] + g_bhh0p[c + 2];
            float rgate = sigmoidf_(gi0 + gh0);
            float zgate = sigmoidf_(gi1 + gh1);
            float nn = tanhf_(gi2 + rgate * gh2);
            float hp = hcur[(size_t)b * H_ + j];
            hnext[(size_t)b * H_ + j] = (1.0f - zgate) * nn + zgate * hp;
        }
    }
}

// ============================================================================
// layer1_k: plain GEMM into scratch. z=0: gi = h_l0 @ Wih1p^T; z=1: gh = h1 @ Whh1p^T
// Same 64-thread fine tiles; 4096 blocks total.
// ============================================================================
__global__ void __launch_bounds__(64) layer1_k(int p) {
    int z = blockIdx.z;
    const float* __restrict__ Amat = z ? g_h1[p ^ 1] : g_h0[p];
    const float* __restrict__ Wmat = z ? g_Whh1p : g_Wih1p;
    float*       __restrict__ Cdst = z ? g_gh : g_gi;

    __shared__ float As[16 * ASTR];
    __shared__ float Bs[16 * BSTR];

    int tid = threadIdx.x;
    int bm = blockIdx.y * 64;
    int c0 = blockIdx.x * 48;
    int rg = (tid >> 3) * 8;
    int cg = (tid & 7) * 6;

    float acc[8][6] = {};

    for (int kt = 0; kt < H_; kt += 16) {
        __syncthreads();
#pragma unroll
        for (int pp = 0; pp < 4; pp++) {
            int r = (tid >> 2) + 16 * pp, kc = (tid & 3) * 4;
            float4 v = *(const float4*)(Amat + (size_t)(bm + r) * H_ + kt + kc);
            As[(kc + 0) * ASTR + r] = v.x;
            As[(kc + 1) * ASTR + r] = v.y;
            As[(kc + 2) * ASTR + r] = v.z;
            As[(kc + 3) * ASTR + r] = v.w;
        }
#pragma unroll
        for (int s = 0; s < 3; s++) {
            int i = tid + 64 * s;
            int col = i >> 2, kc = (i & 3) * 4;
            float4 v = *(const float4*)(Wmat + (size_t)(c0 + col) * H_ + kt + kc);
            Bs[(kc + 0) * BSTR + col] = v.x;
            Bs[(kc + 1) * BSTR + col] = v.y;
            Bs[(kc + 2) * BSTR + col] = v.z;
            Bs[(kc + 3) * BSTR + col] = v.w;
        }
        __syncthreads();
#pragma unroll
        for (int kk = 0; kk < 16; kk++) {
            float a[8], b[6];
            *(float4*)&a[0] = *(const float4*)&As[kk * ASTR + rg];
            *(float4*)&a[4] = *(const float4*)&As[kk * ASTR + rg + 4];
            *(float2*)&b[0] = *(const float2*)&Bs[kk * BSTR + cg];
            *(float2*)&b[2] = *(const float2*)&Bs[kk * BSTR + cg + 2];
            *(float2*)&b[4] = *(const float2*)&Bs[kk * BSTR + cg + 4];
#pragma unroll
            for (int i = 0; i < 8; i++)
#pragma unroll
                for (int j = 0; j < 6; j++) acc[i][j] += a[i] * b[j];
        }
    }
#pragma unroll
    for (int i = 0; i < 8; i++) {
        size_t o = (size_t)(bm + rg + i) * TH3 + c0 + cg;
        *(float2*)&Cdst[o]     = make_float2(acc[i][0], acc[i][1]);
        *(float2*)&Cdst[o + 2] = make_float2(acc[i][2], acc[i][3]);
        *(float2*)&Cdst[o + 4] = make_float2(acc[i][4], acc[i][5]);
    }
}

// ============================================================================
// fuse_k: layer1 GRU epilogue (16 rows x 512 h) + logits GEMM + argmax + token logic
// ============================================================================
__global__ void __launch_bounds__(256) fuse_k(int p, const float* __restrict__ out_b,
                                              float* __restrict__ xout,
                                              float* __restrict__ endp, int step) {
    __shared__ float Hs[16 * H_];       // 32 KB
    __shared__ float Ls[16][129];       // padded: conflict-free argmax scan
    int b0 = blockIdx.x * 16;
    int tid = threadIdx.x;
    const float* __restrict__ hprev = g_h1[p ^ 1];
    float*       __restrict__ hnew  = g_h1[p];

    // phase 1: GRU epilogue for rows b0..b0+15
#pragma unroll
    for (int s = 0; s < 32; s++) {
        int idx = tid + 256 * s;
        int row = idx >> 9, j = idx & 511;
        int b = b0 + row;
        int c = j * 3;
        size_t o = (size_t)b * TH3 + c;
        float gi0 = g_gi[o]     + g_bi1p[c];
        float gi1 = g_gi[o + 1] + g_bi1p[c + 1];
        float gi2 = g_gi[o + 2] + g_bi1p[c + 2];
        float gh0 = g_gh[o]     + g_bh1p[c];
        float gh1 = g_gh[o + 1] + g_bh1p[c + 1];
        float gh2 = g_gh[o + 2] + g_bh1p[c + 2];
        float rgate = sigmoidf_(gi0 + gh0);
        float zgate = sigmoidf_(gi1 + gh1);
        float nn = tanhf_(gi2 + rgate * gh2);
        float hp = hprev[(size_t)b * H_ + j];
        float hv = (1.0f - zgate) * nn + zgate * hp;
        Hs[row * H_ + j] = hv;
        hnew[(size_t)b * H_ + j] = hv;
    }
    __syncthreads();

    // phase 2: logits GEMM (two halves of 8 rows; vt = vocab index)
    int vt = tid & 127, half = tid >> 7;
    float acc[8];
#pragma unroll
    for (int r = 0; r < 8; r++) acc[r] = 0.0f;
    for (int k = 0; k < H_; k += 4) {
        float w0 = g_outWt[(k + 0) * V_ + vt];
        float w1 = g_outWt[(k + 1) * V_ + vt];
        float w2 = g_outWt[(k + 2) * V_ + vt];
        float w3 = g_outWt[(k + 3) * V_ + vt];
#pragma unroll
        for (int r = 0; r < 8; r++) {
            float4 hv = *(const float4*)&Hs[(half * 8 + r) * H_ + k];
            acc[r] += hv.x * w0 + hv.y * w1 + hv.z * w2 + hv.w * w3;
        }
    }
    float bb = out_b[vt];
#pragma unroll
    for (int r = 0; r < 8; r++) Ls[half * 8 + r][vt] = acc[r] + bb;
    __syncthreads();

    // phase 3: argmax + token/eos bookkeeping
    if (tid < 16) {
        int b = b0 + tid;
        const float* row = Ls[tid];
        float best = row[0];
        int bi = 0;
        for (int v = 1; v < V_; v++) {
            float xv = row[v];
            if (xv > best) { best = xv; bi = v; }
        }
        int eo = g_eos[b];
        xout[b * MAXLEN + step] = eo ? 0.0f : (float)bi;
        if (!eo && bi == 2) {
            if (endp) endp[b] = (float)(step + 1);
            g_eos[b] = 1;
        }
        g_w[b] = bi;
    }
}

// ------------------------- launch -------------------------
extern "C" void kernel_launch(void* const* d_in, const int* in_sizes, int n_in,
                              void* d_out, int out_size) {
    static const int want[14] = {
        B_ * D_, V_ * H_, H_ * D_, H_,
        TH3 * (H_ + D_), TH3 * H_, TH3, TH3,
        TH3 * H_, TH3 * H_, TH3, TH3,
        V_ * H_, V_
    };
    const float* in[14];
    bool used[14] = {};
    bool ok = (n_in >= 14);
    for (int i = 0; i < 14 && ok; i++) {
        int found = -1;
        for (int j = 0; j < 14; j++) {
            if (!used[j] && in_sizes[j] == want[i]) { found = j; break; }
        }
        if (found < 0) { ok = false; break; }
        used[found] = true;
        in[i] = (const float*)d_in[found];
    }
    if (!ok) {
        for (int i = 0; i < 14; i++) in[i] = (const float*)d_in[i];
    }
    const float* z     = in[0];
    const float* lat_W = in[2];
    const float* lat_b = in[3];
    const float* out_b = in[13];

    float* xout = (float*)d_out;
    float* endp = nullptr;
    if (out_size >= B_ * MAXLEN + B_) {
        endp = xout + (out_size - B_);
    }

    permute_kernel<<<(TH3 * H_ + 255) / 256, 256>>>(in[4], in[5], in[8], in[9],
                                                    in[6], in[7], in[10], in[11], in[12]);
    init_state_kernel<<<(B_ + 255) / 256, 256>>>(xout, endp);
    gemm_init_kernel<<<dim3(H_ / 64, B_ / 64), 256>>>(z, lat_W, lat_b, 0);
    gemm_init_kernel<<<dim3(TH3 / 64, B_ / 64), 256>>>(z, nullptr, nullptr, 1);
    gemm_init_kernel<<<dim3(TH3 / 64, V_ / 64), 256>>>(in[1], nullptr, nullptr, 2);

    for (int s = 1; s < MAXLEN; s++) {
        int p = s & 1;
        layer0_k<<<dim3(H_ / 16, B_ / 64), 64>>>(p);
        layer1_k<<<dim3(TH3 / 48, B_ / 64, 2), 64>>>(p);
        fuse_k<<<B_ / 16, 256>>>(p, out_b, xout, endp, s);
    }
}